// round 12
// baseline (speedup 1.0000x reference)
#include <cuda_runtime.h>
#include <cuda_bf16.h>
#include <math.h>
#include <stdint.h>

#define NODES 100000
#define EDGES 1600000
#define DIMS  64
#define H2    128
#define NGRAPH 512
#define NLAYER 4
#define BN_EPS 1e-5f

#define SCAN_B 1024
#define SCAN_NB ((NODES + SCAN_B - 1) / SCAN_B)   // 98
#define NTILES ((NODES + 127) / 128)              // 782
#define PGRID 148

typedef unsigned long long u64t;

#define FADD2(acc, b) asm("add.rn.f32x2 %0, %0, %1;" : "+l"(acc) : "l"(b))

__device__ __forceinline__ void mma_bf16(float* c, const uint32_t* a, const uint32_t* b) {
    asm volatile("mma.sync.aligned.m16n8k16.row.col.f32.bf16.bf16.f32 "
        "{%0,%1,%2,%3}, {%4,%5,%6,%7}, {%8,%9}, {%0,%1,%2,%3};"
        : "+f"(c[0]), "+f"(c[1]), "+f"(c[2]), "+f"(c[3])
        : "r"(a[0]), "r"(a[1]), "r"(a[2]), "r"(a[3]), "r"(b[0]), "r"(b[1]));
}

__device__ __forceinline__ void split2(float2 z, uint32_t& hi, uint32_t& lo) {
    __nv_bfloat162 h2 = __float22bfloat162_rn(z);
    float2 res = make_float2(z.x - __low2float(h2), z.y - __high2float(h2));
    __nv_bfloat162 l2 = __float22bfloat162_rn(res);
    hi = *(uint32_t*)&h2;
    lo = *(uint32_t*)&l2;
}

__device__ __forceinline__ int detect_is64(const int* p) {
    int odd_nonzero = 0;
    #pragma unroll
    for (int t = 1; t < 32; t += 2) odd_nonzero |= (p[t] != 0);
    return odd_nonzero ? 0 : 1;
}

__device__ __forceinline__ int clampN(int v) {
    return v < 0 ? 0 : (v >= NODES ? NODES - 1 : v);
}

// ---------------- device scratch ----------------------------------------------
__device__ int   g_batI[NODES];
__device__ int   g_deg[NODES];
__device__ int   g_rowstart[NODES + 1];
__device__ int   g_cursor[NODES];
__device__ int   g_srcsorted[EDGES];
__device__ int   g_bsum[256];

__device__ float g_h[NODES * DIMS];
__device__ uint2 g_zh[NODES * 16];
__device__ uint2 g_zl[NODES * 16];

__device__ uint32_t g_w1h[NLAYER][128 * 32], g_w1l[NLAYER][128 * 32];
__device__ uint32_t g_w2h[NLAYER][64 * 64],  g_w2l[NLAYER][64 * 64];

__device__ float g_alpha1[NLAYER][H2], g_beta1[NLAYER][H2];
__device__ float g_alpha2[NLAYER][DIMS], g_beta2[NLAYER][DIMS];

// ---------------- big prep (unchanged from R11) --------------------------------
#define BATCH_BLKS ((NODES + 255) / 256)
#define HIST_BLKS  ((EDGES / 2 + 255) / 256)
#define W1_BLKS    (NLAYER * 128 * 32 / 256)
#define W2_BLKS    (NLAYER * 64 * 64 / 256)
#define PREP_GRID  (NLAYER + BATCH_BLKS + HIST_BLKS + W1_BLKS + W2_BLKS)

__global__ void big_prep_kernel(const void* __restrict__ ei, const void* __restrict__ bat,
                            const float* __restrict__ W1, const float* __restrict__ W2,
                            const float* __restrict__ b1, const float* __restrict__ g1,
                            const float* __restrict__ bt1, const float* __restrict__ m1,
                            const float* __restrict__ v1,
                            const float* __restrict__ b2, const float* __restrict__ g2,
                            const float* __restrict__ bt2, const float* __restrict__ m2,
                            const float* __restrict__ v2) {
    int bid = blockIdx.x;
    if (bid < NLAYER) {
        int l = bid;
        int c = threadIdx.x;
        if (c < H2) {
            int i = l * H2 + c;
            float s = g1[i] * rsqrtf(v1[i] + BN_EPS);
            g_alpha1[l][c] = s;
            g_beta1[l][c]  = (b1[i] - m1[i]) * s + bt1[i];
        }
        if (c < DIMS) {
            int i = l * DIMS + c;
            float s = g2[i] * rsqrtf(v2[i] + BN_EPS);
            g_alpha2[l][c] = s;
            g_beta2[l][c]  = (b2[i] - m2[i]) * s + bt2[i];
        }
        return;
    }
    bid -= NLAYER;
    if (bid < BATCH_BLKS) {
        __shared__ int s_is64;
        if (threadIdx.x == 0) s_is64 = detect_is64((const int*)ei);
        __syncthreads();
        int i = bid * blockDim.x + threadIdx.x;
        if (i >= NODES) return;
        int b;
        if (s_is64) b = (int)((const long long*)bat)[i];
        else        b = ((const int*)bat)[i];
        g_batI[i] = b < 0 ? 0 : (b >= NGRAPH ? NGRAPH - 1 : b);
        return;
    }
    bid -= BATCH_BLKS;
    if (bid < HIST_BLKS) {
        __shared__ int s_is64;
        if (threadIdx.x == 0) s_is64 = detect_is64((const int*)ei);
        __syncthreads();
        int e0 = (bid * blockDim.x + threadIdx.x) * 2;
        if (e0 >= EDGES) return;
        int d0, d1;
        if (s_is64) {
            longlong2 v = ((const longlong2*)((const long long*)ei + EDGES))[e0 >> 1];
            d0 = (int)v.x; d1 = (int)v.y;
        } else {
            int2 v = ((const int2*)((const int*)ei + EDGES))[e0 >> 1];
            d0 = v.x; d1 = v.y;
        }
        atomicAdd(&g_deg[clampN(d0)], 1);
        atomicAdd(&g_deg[clampN(d1)], 1);
        return;
    }
    bid -= HIST_BLKS;
    if (bid < W1_BLKS) {
        int i = bid * blockDim.x + threadIdx.x;
        int l = i >> 12, rem = i & 4095;
        int n = rem >> 5, kp = rem & 31;
        float2 wv = make_float2(W1[l * DIMS * H2 + (2 * kp) * H2 + n],
                                W1[l * DIMS * H2 + (2 * kp + 1) * H2 + n]);
        uint32_t hi, lo; split2(wv, hi, lo);
        g_w1h[l][rem] = hi;
        g_w1l[l][rem] = lo;
        return;
    }
    bid -= W1_BLKS;
    {
        int i = bid * blockDim.x + threadIdx.x;
        int l = i >> 12, rem = i & 4095;
        int n = rem >> 6, kp = rem & 63;
        float2 wv = make_float2(W2[l * H2 * DIMS + (2 * kp) * DIMS + n],
                                W2[l * H2 * DIMS + (2 * kp + 1) * DIMS + n]);
        uint32_t hi, lo; split2(wv, hi, lo);
        g_w2h[l][rem] = hi;
        g_w2l[l][rem] = lo;
    }
}

// ---------------- scans + fill (unchanged) -------------------------------------
__global__ void scan1_kernel() {
    __shared__ int wsum[32];
    int i = blockIdx.x * SCAN_B + threadIdx.x;
    int lane = threadIdx.x & 31, wid = threadIdx.x >> 5;
    int v = (i < NODES) ? g_deg[i] : 0;
    int x = v;
    #pragma unroll
    for (int off = 1; off < 32; off <<= 1) {
        int t = __shfl_up_sync(0xffffffffu, x, off);
        if (lane >= off) x += t;
    }
    if (lane == 31) wsum[wid] = x;
    __syncthreads();
    if (wid == 0) {
        int s = wsum[lane];
        #pragma unroll
        for (int off = 1; off < 32; off <<= 1) {
            int t = __shfl_up_sync(0xffffffffu, s, off);
            if (lane >= off) s += t;
        }
        wsum[lane] = s;
    }
    __syncthreads();
    int incl = x + (wid > 0 ? wsum[wid - 1] : 0);
    if (i < NODES) g_rowstart[i] = incl - v;
    if (threadIdx.x == SCAN_B - 1) g_bsum[blockIdx.x] = incl;
}

__global__ void scan23_kernel() {
    __shared__ int sh[128];
    int t = threadIdx.x;
    if (t < 128) sh[t] = (t < SCAN_NB) ? g_bsum[t] : 0;
    __syncthreads();
    for (int off = 1; off < 128; off <<= 1) {
        int u = 0;
        if (t < 128 && t >= off) u = sh[t - off];
        __syncthreads();
        if (t < 128) sh[t] += u;
        __syncthreads();
    }
    int add = (blockIdx.x == 0) ? 0 : sh[blockIdx.x - 1];
    int i = blockIdx.x * SCAN_B + t;
    if (i < NODES) {
        int r = g_rowstart[i] + add;
        g_rowstart[i] = r;
        g_cursor[i] = r;
    }
    if (i == 0) g_rowstart[NODES] = EDGES;
}

__global__ void fill_kernel(const void* __restrict__ ei) {
    __shared__ int s_is64;
    if (threadIdx.x == 0) s_is64 = detect_is64((const int*)ei);
    __syncthreads();
    int e0 = (blockIdx.x * blockDim.x + threadIdx.x) * 2;
    if (e0 >= EDGES) return;
    int s0, s1, d0, d1;
    if (s_is64) {
        longlong2 sv = ((const longlong2*)ei)[e0 >> 1];
        longlong2 dv = ((const longlong2*)((const long long*)ei + EDGES))[e0 >> 1];
        s0 = (int)sv.x; s1 = (int)sv.y;
        d0 = (int)dv.x; d1 = (int)dv.y;
    } else {
        int2 sv = ((const int2*)ei)[e0 >> 1];
        int2 dv = ((const int2*)((const int*)ei + EDGES))[e0 >> 1];
        s0 = sv.x; s1 = sv.y;
        d0 = dv.x; d1 = dv.y;
    }
    int p0 = atomicAdd(&g_cursor[clampN(d0)], 1);
    g_srcsorted[p0] = clampN(s0);
    int p1 = atomicAdd(&g_cursor[clampN(d1)], 1);
    g_srcsorted[p1] = clampN(s1);
}

// ---------------- aggregation (unchanged from R11) -----------------------------
__global__ void agg_kernel(const float* __restrict__ hin) {
    int warp = (blockIdx.x * blockDim.x + threadIdx.x) >> 5;
    int lane = threadIdx.x & 31;
    if (warp >= NODES) return;
    int half = lane >> 4;
    int li = lane & 15;
    const float4* __restrict__ h4 = (const float4*)hin;
    float4 acc = make_float4(0.f, 0.f, 0.f, 0.f);
    int rs = g_rowstart[warp], re = g_rowstart[warp + 1];
    for (int base = rs; base < re; base += 32) {
        int cnt = re - base; if (cnt > 32) cnt = 32;
        int s = (base + lane < re) ? g_srcsorted[base + lane] : 0;
        for (int t = 0; t < cnt; t += 2) {
            int idx = t + half;
            int ss = __shfl_sync(0xffffffffu, s, idx);
            if (idx < cnt) {
                float4 v = h4[ss * 16 + li];
                FADD2(*(u64t*)&acc.x, *(u64t*)&v.x);
                FADD2(*(u64t*)&acc.z, *(u64t*)&v.z);
            }
        }
    }
    acc.x += __shfl_down_sync(0xffffffffu, acc.x, 16);
    acc.y += __shfl_down_sync(0xffffffffu, acc.y, 16);
    acc.z += __shfl_down_sync(0xffffffffu, acc.z, 16);
    acc.w += __shfl_down_sync(0xffffffffu, acc.w, 16);
    if (half == 0) {
        float4 self = h4[warp * 16 + li];
        acc.x += self.x; acc.y += self.y; acc.z += self.z; acc.w += self.w;
        uint2 hv, lv;
        split2(make_float2(acc.x, acc.y), hv.x, lv.x);
        split2(make_float2(acc.z, acc.w), hv.y, lv.y);
        g_zh[warp * 16 + li] = hv;
        g_zl[warp * 16 + li] = lv;
    }
}

// ================= persistent fused GEMM1+GEMM2 ================================
// 1 CTA/SM, 512 threads (16 warps), weights resident, z double-buffered.
// smem u32: W1h[4608] W1l[4608] W2h[4352] W2l[4352] zbuf[2*9216] tAh[8704] tAl[8704]
#define SP1 36
#define SP2 68
#define ZBUF_U32 (128 * SP1 * 2)                 // 9216 (zh + zl)
#define P_SMEM ((2 * 4608 + 2 * 4352 + 2 * ZBUF_U32 + 2 * 8704) * 4)  // 215040 B

__device__ __forceinline__ void load_z_tile(uint32_t* zAh, uint32_t* zAl, int m0, int tid) {
    for (int i = tid; i < 128 * 16; i += 512) {
        int r = i >> 4, j = i & 15;
        int node = m0 + r;
        uint2 hv = make_uint2(0u, 0u), lv = make_uint2(0u, 0u);
        if (node < NODES) { hv = g_zh[node * 16 + j]; lv = g_zl[node * 16 + j]; }
        zAh[r * SP1 + 2 * j]     = hv.x;
        zAh[r * SP1 + 2 * j + 1] = hv.y;
        zAl[r * SP1 + 2 * j]     = lv.x;
        zAl[r * SP1 + 2 * j + 1] = lv.y;
    }
}

__global__ void __launch_bounds__(512, 1) gemm12_kernel(int layer, int relu)
{
    extern __shared__ uint32_t sm4[];
    uint32_t* W1h  = sm4;
    uint32_t* W1l  = W1h + 4608;
    uint32_t* W2h  = W1l + 4608;
    uint32_t* W2l  = W2h + 4352;
    uint32_t* zbuf = W2l + 4352;
    uint32_t* tAh  = zbuf + 2 * ZBUF_U32;
    uint32_t* tAl  = tAh + 8704;

    int tid = threadIdx.x;

    // ---- weights: load once ----
    for (int i = tid; i < 128 * 8; i += 512) {      // W1 rows: 8 uint4 each
        int n = i >> 3, j = i & 7;
        uint4 vh = ((const uint4*)g_w1h[layer])[i];
        uint4 vl = ((const uint4*)g_w1l[layer])[i];
        uint32_t o = n * SP1 + 4 * j;
        W1h[o] = vh.x; W1h[o + 1] = vh.y; W1h[o + 2] = vh.z; W1h[o + 3] = vh.w;
        W1l[o] = vl.x; W1l[o + 1] = vl.y; W1l[o + 2] = vl.z; W1l[o + 3] = vl.w;
    }
    for (int i = tid; i < 64 * 16; i += 512) {      // W2 rows: 16 uint4 each
        int n = i >> 4, j = i & 15;
        uint4 vh = ((const uint4*)g_w2h[layer])[i];
        uint4 vl = ((const uint4*)g_w2l[layer])[i];
        uint32_t o = n * SP2 + 4 * j;
        W2h[o] = vh.x; W2h[o + 1] = vh.y; W2h[o + 2] = vh.z; W2h[o + 3] = vh.w;
        W2l[o] = vl.x; W2l[o + 1] = vl.y; W2l[o + 2] = vl.z; W2l[o + 3] = vl.w;
    }
    // ---- first z tile ----
    int tile = blockIdx.x;
    if (tile < NTILES) load_z_tile(zbuf, zbuf + 128 * SP1, tile * 128, tid);
    __syncthreads();

    int w = tid >> 5, lane = tid & 31;
    int mg = w & 3, ng = w >> 2;          // ng in [0,4)
    int Rb = mg * 32;
    int r = lane >> 2, q = lane & 3;
    int parity = 0;

    for (; tile < NTILES; tile += PGRID) {
        uint32_t* zAh = zbuf + parity * ZBUF_U32;
        uint32_t* zAl = zAh + 128 * SP1;
        int m0 = tile * 128;

        // ---- GEMM1: warp tile 32 rows x 32 cols ----
        {
            int Nb = ng * 32;
            float acc[2][4][4];
            #pragma unroll
            for (int mt = 0; mt < 2; mt++)
                #pragma unroll
                for (int nt = 0; nt < 4; nt++)
                    #pragma unroll
                    for (int e = 0; e < 4; e++) acc[mt][nt][e] = 0.f;

            #pragma unroll
            for (int ch = 0; ch < 4; ch++) {
                int K2 = ch * 8;
                uint32_t ah[2][4], al[2][4];
                #pragma unroll
                for (int mt = 0; mt < 2; mt++) {
                    int base = (Rb + mt * 16 + r) * SP1 + K2 + q;
                    ah[mt][0] = zAh[base];
                    ah[mt][1] = zAh[base + 8 * SP1];
                    ah[mt][2] = zAh[base + 4];
                    ah[mt][3] = zAh[base + 8 * SP1 + 4];
                    al[mt][0] = zAl[base];
                    al[mt][1] = zAl[base + 8 * SP1];
                    al[mt][2] = zAl[base + 4];
                    al[mt][3] = zAl[base + 8 * SP1 + 4];
                }
                #pragma unroll
                for (int nt = 0; nt < 4; nt++) {
                    int nb = (Nb + nt * 8 + r) * SP1 + K2 + q;
                    uint32_t bh[2] = { W1h[nb], W1h[nb + 4] };
                    uint32_t bl[2] = { W1l[nb], W1l[nb + 4] };
                    #pragma unroll
                    for (int mt = 0; mt < 2; mt++) {
                        mma_bf16(acc[mt][nt], ah[mt], bh);
                        mma_bf16(acc[mt][nt], ah[mt], bl);
                        mma_bf16(acc[mt][nt], al[mt], bh);
                    }
                }
            }

            // t store (dedicated region; last iteration's GEMM2 done per end-sync)
            #pragma unroll
            for (int nt = 0; nt < 4; nt++) {
                int col = Nb + nt * 8 + q * 2;
                int kp = col >> 1;
                float2 al2 = *(const float2*)&g_alpha1[layer][col];
                float2 be2 = *(const float2*)&g_beta1[layer][col];
                #pragma unroll
                for (int mt = 0; mt < 2; mt++) {
                    int row0 = Rb + mt * 16 + r;
                    float2 o0, o1;
                    o0.x = fmaxf(fmaf(acc[mt][nt][0], al2.x, be2.x), 0.f);
                    o0.y = fmaxf(fmaf(acc[mt][nt][1], al2.y, be2.y), 0.f);
                    o1.x = fmaxf(fmaf(acc[mt][nt][2], al2.x, be2.x), 0.f);
                    o1.y = fmaxf(fmaf(acc[mt][nt][3], al2.y, be2.y), 0.f);
                    uint32_t hi, lo;
                    split2(o0, hi, lo);
                    tAh[row0 * SP2 + kp] = hi;
                    tAl[row0 * SP2 + kp] = lo;
                    split2(o1, hi, lo);
                    tAh[(row0 + 8) * SP2 + kp] = hi;
                    tAl[(row0 + 8) * SP2 + kp] = lo;
                }
            }
        }

        // ---- prefetch next z into the other buffer (overlaps GEMM2) ----
        int tile2 = tile + PGRID;
        if (tile2 < NTILES)
            load_z_tile(zbuf + (parity ^ 1) * ZBUF_U32,
                        zbuf + (parity ^ 1) * ZBUF_U32 + 128 * SP1, tile2 * 128, tid);

        __syncthreads();   // t visible to all; prefetch stores done

        // ---- GEMM2: warp tile 32 rows x 16 cols ----
        {
            int Nb2 = ng * 16;
            float acc[2][2][4];
            #pragma unroll
            for (int mt = 0; mt < 2; mt++)
                #pragma unroll
                for (int nt = 0; nt < 2; nt++)
                    #pragma unroll
                    for (int e = 0; e < 4; e++) acc[mt][nt][e] = 0.f;

            #pragma unroll
            for (int ch = 0; ch < 8; ch++) {
                int K2 = ch * 8;
                uint32_t ah[2][4], al[2][4];
                #pragma unroll
                for (int mt = 0; mt < 2; mt++) {
                    int base = (Rb + mt * 16 + r) * SP2 + K2 + q;
                    ah[mt][0] = tAh[base];
                    ah[mt][1] = tAh[base + 8 * SP2];
                    ah[mt][2] = tAh[base + 4];
                    ah[mt][3] = tAh[base + 8 * SP2 + 4];
                    al[mt][0] = tAl[base];
                    al[mt][1] = tAl[base + 8 * SP2];
                    al[mt][2] = tAl[base + 4];
                    al[mt][3] = tAl[base + 8 * SP2 + 4];
                }
                #pragma unroll
                for (int nt = 0; nt < 2; nt++) {
                    int nb = (Nb2 + nt * 8 + r) * SP2 + K2 + q;
                    uint32_t bh[2] = { W2h[nb], W2h[nb + 4] };
                    uint32_t bl[2] = { W2l[nb], W2l[nb + 4] };
                    #pragma unroll
                    for (int mt = 0; mt < 2; mt++) {
                        mma_bf16(acc[mt][nt], ah[mt], bh);
                        mma_bf16(acc[mt][nt], ah[mt], bl);
                        mma_bf16(acc[mt][nt], al[mt], bh);
                    }
                }
            }

            #pragma unroll
            for (int nt = 0; nt < 2; nt++) {
                int col = Nb2 + nt * 8 + q * 2;
                float2 al2 = *(const float2*)&g_alpha2[layer][col];
                float2 be2 = *(const float2*)&g_beta2[layer][col];
                #pragma unroll
                for (int mt = 0; mt < 2; mt++) {
                    int row0 = m0 + Rb + mt * 16 + r;
                    if (row0 < NODES) {
                        float2 o;
                        float v0 = fmaf(acc[mt][nt][0], al2.x, be2.x);
                        float v1 = fmaf(acc[mt][nt][1], al2.y, be2.y);
                        o.x = relu ? fmaxf(v0, 0.f) : v0;
                        o.y = relu ? fmaxf(v1, 0.f) : v1;
                        *(float2*)&g_h[row0 * DIMS + col] = o;
                    }
                    int row1 = row0 + 8;
                    if (row1 < NODES) {
                        float2 o;
                        float v2 = fmaf(acc[mt][nt][2], al2.x, be2.x);
                        float v3 = fmaf(acc[mt][nt][3], al2.y, be2.y);
                        o.x = relu ? fmaxf(v2, 0.f) : v2;
                        o.y = relu ? fmaxf(v3, 0.f) : v3;
                        *(float2*)&g_h[row1 * DIMS + col] = o;
                    }
                }
            }
        }
        __syncthreads();   // protect t + z buffer for next iteration
        parity ^= 1;
    }
}

// ---------------- global mean pool ---------------------------------------------
__global__ void __launch_bounds__(256) pool_kernel(float* __restrict__ out) {
    __shared__ float red[256];
    int g = blockIdx.x;
    int tid = threadIdx.x;
    int d = tid & 63;
    int rg = tid >> 6;
    int lo = 0, hi = NODES;
    while (lo < hi) { int mid = (lo + hi) >> 1; if (g_batI[mid] < g) lo = mid + 1; else hi = mid; }
    int start = lo;
    lo = start; hi = NODES;
    while (lo < hi) { int mid = (lo + hi) >> 1; if (g_batI[mid] < g + 1) lo = mid + 1; else hi = mid; }
    int end = lo;
    float s = 0.f;
    for (int n = start + rg; n < end; n += 4) s += g_h[n * DIMS + d];
    red[tid] = s;
    __syncthreads();
    if (rg == 0) {
        s = red[d] + red[d + 64] + red[d + 128] + red[d + 192];
        float cnt = (float)(end - start);
        out[g * DIMS + d] = s / fmaxf(cnt, 1.0f);
    }
}

// ---------------- launch --------------------------------------------------------
extern "C" void kernel_launch(void* const* d_in, const int* in_sizes, int n_in,
                              void* d_out, int out_size) {
    const float* x    = (const float*)d_in[0];
    const void*  ei   = d_in[1];
    const void*  bat  = d_in[2];
    const float* W1   = (const float*)d_in[3];
    const float* b1   = (const float*)d_in[4];
    const float* g1   = (const float*)d_in[5];
    const float* bt1  = (const float*)d_in[6];
    const float* m1   = (const float*)d_in[7];
    const float* v1   = (const float*)d_in[8];
    const float* W2   = (const float*)d_in[9];
    const float* b2   = (const float*)d_in[10];
    const float* g2   = (const float*)d_in[11];
    const float* bt2  = (const float*)d_in[12];
    const float* m2   = (const float*)d_in[13];
    const float* v2   = (const float*)d_in[14];
    float* out = (float*)d_out;

    cudaFuncSetAttribute(gemm12_kernel, cudaFuncAttributeMaxDynamicSharedMemorySize, P_SMEM);

    static int* dDeg = nullptr;
    static float* dH = nullptr;
    if (!dDeg) {
        cudaGetSymbolAddress((void**)&dDeg, g_deg);
        cudaGetSymbolAddress((void**)&dH, g_h);
    }

    cudaMemsetAsync(dDeg, 0, NODES * sizeof(int));
    big_prep_kernel<<<PREP_GRID, 256>>>(ei, bat, W1, W2,
        b1, g1, bt1, m1, v1, b2, g2, bt2, m2, v2);                // k1
    scan1_kernel<<<SCAN_NB, SCAN_B>>>();                           // k2
    scan23_kernel<<<SCAN_NB, SCAN_B>>>();                          // k3
    fill_kernel<<<(EDGES / 2 + 255) / 256, 256>>>(ei);             // k4 (ncu capture)

    for (int l = 0; l < NLAYER; l++) {
        const float* hin = (l == 0) ? x : (const float*)dH;
        agg_kernel<<<(NODES * 32 + 255) / 256, 256>>>(hin);
        gemm12_kernel<<<PGRID, 512, P_SMEM>>>(l, (l != NLAYER - 1) ? 1 : 0);
    }

    pool_kernel<<<NGRAPH, 256>>>(out);
}

// round 13
// speedup vs baseline: 1.4974x; 1.4974x over previous
#include <cuda_runtime.h>
#include <cuda_bf16.h>
#include <math.h>
#include <stdint.h>

#define NODES 100000
#define EDGES 1600000
#define DIMS  64
#define H2    128
#define NGRAPH 512
#define NLAYER 4
#define BN_EPS 1e-5f

#define SCAN_B 1024
#define SCAN_NB ((NODES + SCAN_B - 1) / SCAN_B)   // 98
#define NTILES ((NODES + 127) / 128)              // 782
#define GTILES ((NTILES + 1) / 2)                 // 391

typedef unsigned long long u64t;

#define FADD2(acc, b) asm("add.rn.f32x2 %0, %0, %1;" : "+l"(acc) : "l"(b))

__device__ __forceinline__ void mma_bf16(float* c, const uint32_t* a, const uint32_t* b) {
    asm volatile("mma.sync.aligned.m16n8k16.row.col.f32.bf16.bf16.f32 "
        "{%0,%1,%2,%3}, {%4,%5,%6,%7}, {%8,%9}, {%0,%1,%2,%3};"
        : "+f"(c[0]), "+f"(c[1]), "+f"(c[2]), "+f"(c[3])
        : "r"(a[0]), "r"(a[1]), "r"(a[2]), "r"(a[3]), "r"(b[0]), "r"(b[1]));
}

__device__ __forceinline__ void split2(float2 z, uint32_t& hi, uint32_t& lo) {
    __nv_bfloat162 h2 = __float22bfloat162_rn(z);
    float2 res = make_float2(z.x - __low2float(h2), z.y - __high2float(h2));
    __nv_bfloat162 l2 = __float22bfloat162_rn(res);
    hi = *(uint32_t*)&h2;
    lo = *(uint32_t*)&l2;
}

__device__ __forceinline__ int detect_is64(const int* p) {
    int odd_nonzero = 0;
    #pragma unroll
    for (int t = 1; t < 32; t += 2) odd_nonzero |= (p[t] != 0);
    return odd_nonzero ? 0 : 1;
}

__device__ __forceinline__ int clampN(int v) {
    return v < 0 ? 0 : (v >= NODES ? NODES - 1 : v);
}

// ---------------- device scratch ----------------------------------------------
__device__ int   g_batI[NODES];
__device__ int   g_deg[NODES];
__device__ int   g_rowstart[NODES + 1];
__device__ int   g_cursor[NODES];
__device__ int   g_srcsorted[EDGES];
__device__ int   g_bsum[256];

__device__ float g_h[NODES * DIMS];
__device__ uint2 g_zh[NODES * 16];
__device__ uint2 g_zl[NODES * 16];

__device__ uint32_t g_w1h[NLAYER][128 * 32], g_w1l[NLAYER][128 * 32];
__device__ uint32_t g_w2h[NLAYER][64 * 64],  g_w2l[NLAYER][64 * 64];

__device__ float g_alpha1[NLAYER][H2], g_beta1[NLAYER][H2];
__device__ float g_alpha2[NLAYER][DIMS], g_beta2[NLAYER][DIMS];

// ---------------- big prep ------------------------------------------------------
#define BATCH_BLKS ((NODES + 255) / 256)
#define HIST_BLKS  ((EDGES / 2 + 255) / 256)
#define W1_BLKS    (NLAYER * 128 * 32 / 256)
#define W2_BLKS    (NLAYER * 64 * 64 / 256)
#define PREP_GRID  (NLAYER + BATCH_BLKS + HIST_BLKS + W1_BLKS + W2_BLKS)

__global__ void big_prep_kernel(const void* __restrict__ ei, const void* __restrict__ bat,
                            const float* __restrict__ W1, const float* __restrict__ W2,
                            const float* __restrict__ b1, const float* __restrict__ g1,
                            const float* __restrict__ bt1, const float* __restrict__ m1,
                            const float* __restrict__ v1,
                            const float* __restrict__ b2, const float* __restrict__ g2,
                            const float* __restrict__ bt2, const float* __restrict__ m2,
                            const float* __restrict__ v2) {
    int bid = blockIdx.x;
    if (bid < NLAYER) {
        int l = bid;
        int c = threadIdx.x;
        if (c < H2) {
            int i = l * H2 + c;
            float s = g1[i] * rsqrtf(v1[i] + BN_EPS);
            g_alpha1[l][c] = s;
            g_beta1[l][c]  = (b1[i] - m1[i]) * s + bt1[i];
        }
        if (c < DIMS) {
            int i = l * DIMS + c;
            float s = g2[i] * rsqrtf(v2[i] + BN_EPS);
            g_alpha2[l][c] = s;
            g_beta2[l][c]  = (b2[i] - m2[i]) * s + bt2[i];
        }
        return;
    }
    bid -= NLAYER;
    if (bid < BATCH_BLKS) {
        __shared__ int s_is64;
        if (threadIdx.x == 0) s_is64 = detect_is64((const int*)ei);
        __syncthreads();
        int i = bid * blockDim.x + threadIdx.x;
        if (i >= NODES) return;
        int b;
        if (s_is64) b = (int)((const long long*)bat)[i];
        else        b = ((const int*)bat)[i];
        g_batI[i] = b < 0 ? 0 : (b >= NGRAPH ? NGRAPH - 1 : b);
        return;
    }
    bid -= BATCH_BLKS;
    if (bid < HIST_BLKS) {
        __shared__ int s_is64;
        if (threadIdx.x == 0) s_is64 = detect_is64((const int*)ei);
        __syncthreads();
        int e0 = (bid * blockDim.x + threadIdx.x) * 2;
        if (e0 >= EDGES) return;
        int d0, d1;
        if (s_is64) {
            longlong2 v = ((const longlong2*)((const long long*)ei + EDGES))[e0 >> 1];
            d0 = (int)v.x; d1 = (int)v.y;
        } else {
            int2 v = ((const int2*)((const int*)ei + EDGES))[e0 >> 1];
            d0 = v.x; d1 = v.y;
        }
        atomicAdd(&g_deg[clampN(d0)], 1);
        atomicAdd(&g_deg[clampN(d1)], 1);
        return;
    }
    bid -= HIST_BLKS;
    if (bid < W1_BLKS) {
        int i = bid * blockDim.x + threadIdx.x;
        int l = i >> 12, rem = i & 4095;
        int n = rem >> 5, kp = rem & 31;
        float2 wv = make_float2(W1[l * DIMS * H2 + (2 * kp) * H2 + n],
                                W1[l * DIMS * H2 + (2 * kp + 1) * H2 + n]);
        uint32_t hi, lo; split2(wv, hi, lo);
        g_w1h[l][rem] = hi;
        g_w1l[l][rem] = lo;
        return;
    }
    bid -= W1_BLKS;
    {
        int i = bid * blockDim.x + threadIdx.x;
        int l = i >> 12, rem = i & 4095;
        int n = rem >> 6, kp = rem & 63;
        float2 wv = make_float2(W2[l * H2 * DIMS + (2 * kp) * DIMS + n],
                                W2[l * H2 * DIMS + (2 * kp + 1) * DIMS + n]);
        uint32_t hi, lo; split2(wv, hi, lo);
        g_w2h[l][rem] = hi;
        g_w2l[l][rem] = lo;
    }
}

// ---------------- scans + fill --------------------------------------------------
__global__ void scan1_kernel() {
    __shared__ int wsum[32];
    int i = blockIdx.x * SCAN_B + threadIdx.x;
    int lane = threadIdx.x & 31, wid = threadIdx.x >> 5;
    int v = (i < NODES) ? g_deg[i] : 0;
    int x = v;
    #pragma unroll
    for (int off = 1; off < 32; off <<= 1) {
        int t = __shfl_up_sync(0xffffffffu, x, off);
        if (lane >= off) x += t;
    }
    if (lane == 31) wsum[wid] = x;
    __syncthreads();
    if (wid == 0) {
        int s = wsum[lane];
        #pragma unroll
        for (int off = 1; off < 32; off <<= 1) {
            int t = __shfl_up_sync(0xffffffffu, s, off);
            if (lane >= off) s += t;
        }
        wsum[lane] = s;
    }
    __syncthreads();
    int incl = x + (wid > 0 ? wsum[wid - 1] : 0);
    if (i < NODES) g_rowstart[i] = incl - v;
    if (threadIdx.x == SCAN_B - 1) g_bsum[blockIdx.x] = incl;
}

__global__ void scan23_kernel() {
    __shared__ int sh[128];
    int t = threadIdx.x;
    if (t < 128) sh[t] = (t < SCAN_NB) ? g_bsum[t] : 0;
    __syncthreads();
    for (int off = 1; off < 128; off <<= 1) {
        int u = 0;
        if (t < 128 && t >= off) u = sh[t - off];
        __syncthreads();
        if (t < 128) sh[t] += u;
        __syncthreads();
    }
    int add = (blockIdx.x == 0) ? 0 : sh[blockIdx.x - 1];
    int i = blockIdx.x * SCAN_B + t;
    if (i < NODES) {
        int r = g_rowstart[i] + add;
        g_rowstart[i] = r;
        g_cursor[i] = r;
    }
    if (i == 0) g_rowstart[NODES] = EDGES;
}

__global__ void fill_kernel(const void* __restrict__ ei) {
    __shared__ int s_is64;
    if (threadIdx.x == 0) s_is64 = detect_is64((const int*)ei);
    __syncthreads();
    int e0 = (blockIdx.x * blockDim.x + threadIdx.x) * 2;
    if (e0 >= EDGES) return;
    int s0, s1, d0, d1;
    if (s_is64) {
        longlong2 sv = ((const longlong2*)ei)[e0 >> 1];
        longlong2 dv = ((const longlong2*)((const long long*)ei + EDGES))[e0 >> 1];
        s0 = (int)sv.x; s1 = (int)sv.y;
        d0 = (int)dv.x; d1 = (int)dv.y;
    } else {
        int2 sv = ((const int2*)ei)[e0 >> 1];
        int2 dv = ((const int2*)((const int*)ei + EDGES))[e0 >> 1];
        s0 = sv.x; s1 = sv.y;
        d0 = dv.x; d1 = dv.y;
    }
    int p0 = atomicAdd(&g_cursor[clampN(d0)], 1);
    g_srcsorted[p0] = clampN(s0);
    int p1 = atomicAdd(&g_cursor[clampN(d1)], 1);
    g_srcsorted[p1] = clampN(s1);
}

// ---------------- aggregation ---------------------------------------------------
__global__ void agg_kernel(const float* __restrict__ hin) {
    int warp = (blockIdx.x * blockDim.x + threadIdx.x) >> 5;
    int lane = threadIdx.x & 31;
    if (warp >= NODES) return;
    int half = lane >> 4;
    int li = lane & 15;
    const float4* __restrict__ h4 = (const float4*)hin;
    float4 acc = make_float4(0.f, 0.f, 0.f, 0.f);
    int rs = g_rowstart[warp], re = g_rowstart[warp + 1];
    for (int base = rs; base < re; base += 32) {
        int cnt = re - base; if (cnt > 32) cnt = 32;
        int s = (base + lane < re) ? g_srcsorted[base + lane] : 0;
        for (int t = 0; t < cnt; t += 2) {
            int idx = t + half;
            int ss = __shfl_sync(0xffffffffu, s, idx);
            if (idx < cnt) {
                float4 v = h4[ss * 16 + li];
                FADD2(*(u64t*)&acc.x, *(u64t*)&v.x);
                FADD2(*(u64t*)&acc.z, *(u64t*)&v.z);
            }
        }
    }
    acc.x += __shfl_down_sync(0xffffffffu, acc.x, 16);
    acc.y += __shfl_down_sync(0xffffffffu, acc.y, 16);
    acc.z += __shfl_down_sync(0xffffffffu, acc.z, 16);
    acc.w += __shfl_down_sync(0xffffffffu, acc.w, 16);
    if (half == 0) {
        float4 self = h4[warp * 16 + li];
        acc.x += self.x; acc.y += self.y; acc.z += self.z; acc.w += self.w;
        uint2 hv, lv;
        split2(make_float2(acc.x, acc.y), hv.x, lv.x);
        split2(make_float2(acc.z, acc.w), hv.y, lv.y);
        g_zh[warp * 16 + li] = hv;
        g_zl[warp * 16 + li] = lv;
    }
}

// ================= fused GEMM1+GEMM2 (R11 inner code, 2 tiles per CTA) =========
#define SP1 36
#define SP2 68
#define L_SMEM ((4 * 128 * SP1 + 2 * 64 * SP2) * 4)   // 108544 B

__global__ void __launch_bounds__(256, 2) gemm12_kernel(int layer, int relu)
{
    extern __shared__ uint32_t sm4[];
    uint32_t* zAh = sm4;
    uint32_t* zAl = zAh + 128 * SP1;
    uint32_t* W1h = zAl + 128 * SP1;
    uint32_t* W1l = W1h + 128 * SP1;
    uint32_t* W2h = W1l + 128 * SP1;
    uint32_t* W2l = W2h + 64 * SP2;
    uint32_t* tAh = sm4;               // aliases z+W1 after GEMM1
    uint32_t* tAl = tAh + 128 * SP2;

    int tid = threadIdx.x;
    int w = tid >> 5, lane = tid & 31;
    int mg = w & 3, ng = w >> 2;
    int Rb = mg * 32;
    int r = lane >> 2, q = lane & 3;

    for (int tt = 0; tt < 2; tt++) {
        int tile = blockIdx.x + tt * GTILES;
        if (tile >= NTILES) break;
        int m0 = tile * 128;

        // z fill (region was t last iteration -> sync at loop end protects)
        for (int i = tid; i < 128 * 16; i += 256) {
            int rr = i >> 4, j = i & 15;
            int node = m0 + rr;
            uint2 hv = make_uint2(0u, 0u), lv = make_uint2(0u, 0u);
            if (node < NODES) { hv = g_zh[node * 16 + j]; lv = g_zl[node * 16 + j]; }
            zAh[rr * SP1 + 2 * j]     = hv.x;
            zAh[rr * SP1 + 2 * j + 1] = hv.y;
            zAl[rr * SP1 + 2 * j]     = lv.x;
            zAl[rr * SP1 + 2 * j + 1] = lv.y;
        }
        // W1 fill (aliased by t, must reload every tile)
        for (int i = tid; i < 128 * 8; i += 256) {
            int n = i >> 3, j = i & 7;
            uint4 vh = ((const uint4*)g_w1h[layer])[i];
            uint4 vl = ((const uint4*)g_w1l[layer])[i];
            uint32_t o = n * SP1 + 4 * j;
            W1h[o] = vh.x; W1h[o + 1] = vh.y; W1h[o + 2] = vh.z; W1h[o + 3] = vh.w;
            W1l[o] = vl.x; W1l[o + 1] = vl.y; W1l[o + 2] = vl.z; W1l[o + 3] = vl.w;
        }
        // W2 fill only on first tile (dedicated region stays resident)
        if (tt == 0) {
            for (int i = tid; i < 64 * 16; i += 256) {
                int n = i >> 4, j = i & 15;
                uint4 vh = ((const uint4*)g_w2h[layer])[i];
                uint4 vl = ((const uint4*)g_w2l[layer])[i];
                uint32_t o = n * SP2 + 4 * j;
                W2h[o] = vh.x; W2h[o + 1] = vh.y; W2h[o + 2] = vh.z; W2h[o + 3] = vh.w;
                W2l[o] = vl.x; W2l[o + 1] = vl.y; W2l[o + 2] = vl.z; W2l[o + 3] = vl.w;
            }
        }
        __syncthreads();

        // ---- GEMM1 [128,64]@[64,128] -> t smem ----
        {
            int Nb = ng * 64;
            float acc[2][8][4];
            #pragma unroll
            for (int mt = 0; mt < 2; mt++)
                #pragma unroll
                for (int nt = 0; nt < 8; nt++)
                    #pragma unroll
                    for (int e = 0; e < 4; e++) acc[mt][nt][e] = 0.f;

            #pragma unroll
            for (int ch = 0; ch < 4; ch++) {
                int K2 = ch * 8;
                uint32_t ah[2][4], al[2][4];
                #pragma unroll
                for (int mt = 0; mt < 2; mt++) {
                    int base = (Rb + mt * 16 + r) * SP1 + K2 + q;
                    ah[mt][0] = zAh[base];
                    ah[mt][1] = zAh[base + 8 * SP1];
                    ah[mt][2] = zAh[base + 4];
                    ah[mt][3] = zAh[base + 8 * SP1 + 4];
                    al[mt][0] = zAl[base];
                    al[mt][1] = zAl[base + 8 * SP1];
                    al[mt][2] = zAl[base + 4];
                    al[mt][3] = zAl[base + 8 * SP1 + 4];
                }
                #pragma unroll
                for (int nt = 0; nt < 8; nt++) {
                    int nb = (Nb + nt * 8 + r) * SP1 + K2 + q;
                    uint32_t bh[2] = { W1h[nb], W1h[nb + 4] };
                    uint32_t bl[2] = { W1l[nb], W1l[nb + 4] };
                    #pragma unroll
                    for (int mt = 0; mt < 2; mt++) {
                        mma_bf16(acc[mt][nt], ah[mt], bh);
                        mma_bf16(acc[mt][nt], ah[mt], bl);
                        mma_bf16(acc[mt][nt], al[mt], bh);
                    }
                }
            }
            __syncthreads();   // z/W1 dead -> reuse for t

            #pragma unroll
            for (int nt = 0; nt < 8; nt++) {
                int col = Nb + nt * 8 + q * 2;
                int kp = col >> 1;
                float2 al2 = *(const float2*)&g_alpha1[layer][col];
                float2 be2 = *(const float2*)&g_beta1[layer][col];
                #pragma unroll
                for (int mt = 0; mt < 2; mt++) {
                    int row0 = Rb + mt * 16 + r;
                    float2 o0, o1;
                    o0.x = fmaxf(fmaf(acc[mt][nt][0], al2.x, be2.x), 0.f);
                    o0.y = fmaxf(fmaf(acc[mt][nt][1], al2.y, be2.y), 0.f);
                    o1.x = fmaxf(fmaf(acc[mt][nt][2], al2.x, be2.x), 0.f);
                    o1.y = fmaxf(fmaf(acc[mt][nt][3], al2.y, be2.y), 0.f);
                    uint32_t hi, lo;
                    split2(o0, hi, lo);
                    tAh[row0 * SP2 + kp] = hi;
                    tAl[row0 * SP2 + kp] = lo;
                    split2(o1, hi, lo);
                    tAh[(row0 + 8) * SP2 + kp] = hi;
                    tAl[(row0 + 8) * SP2 + kp] = lo;
                }
            }
        }
        __syncthreads();

        // ---- GEMM2 [128,128]@[128,64] -> g_h ----
        {
            int Nb = ng * 32;
            float acc[2][4][4];
            #pragma unroll
            for (int mt = 0; mt < 2; mt++)
                #pragma unroll
                for (int nt = 0; nt < 4; nt++)
                    #pragma unroll
                    for (int e = 0; e < 4; e++) acc[mt][nt][e] = 0.f;

            #pragma unroll
            for (int ch = 0; ch < 8; ch++) {
                int K2 = ch * 8;
                uint32_t ah[2][4], al[2][4];
                #pragma unroll
                for (int mt = 0; mt < 2; mt++) {
                    int base = (Rb + mt * 16 + r) * SP2 + K2 + q;
                    ah[mt][0] = tAh[base];
                    ah[mt][1] = tAh[base + 8 * SP2];
                    ah[mt][2] = tAh[base + 4];
                    ah[mt][3] = tAh[base + 8 * SP2 + 4];
                    al[mt][0] = tAl[base];
                    al[mt][1] = tAl[base + 8 * SP2];
                    al[mt][2] = tAl[base + 4];
                    al[mt][3] = tAl[base + 8 * SP2 + 4];
                }
                #pragma unroll
                for (int nt = 0; nt < 4; nt++) {
                    int nb = (Nb + nt * 8 + r) * SP2 + K2 + q;
                    uint32_t bh[2] = { W2h[nb], W2h[nb + 4] };
                    uint32_t bl[2] = { W2l[nb], W2l[nb + 4] };
                    #pragma unroll
                    for (int mt = 0; mt < 2; mt++) {
                        mma_bf16(acc[mt][nt], ah[mt], bh);
                        mma_bf16(acc[mt][nt], ah[mt], bl);
                        mma_bf16(acc[mt][nt], al[mt], bh);
                    }
                }
            }

            #pragma unroll
            for (int nt = 0; nt < 4; nt++) {
                int col = Nb + nt * 8 + q * 2;
                float2 al2 = *(const float2*)&g_alpha2[layer][col];
                float2 be2 = *(const float2*)&g_beta2[layer][col];
                #pragma unroll
                for (int mt = 0; mt < 2; mt++) {
                    int row0 = m0 + Rb + mt * 16 + r;
                    if (row0 < NODES) {
                        float2 o;
                        float v0 = fmaf(acc[mt][nt][0], al2.x, be2.x);
                        float v1 = fmaf(acc[mt][nt][1], al2.y, be2.y);
                        o.x = relu ? fmaxf(v0, 0.f) : v0;
                        o.y = relu ? fmaxf(v1, 0.f) : v1;
                        *(float2*)&g_h[row0 * DIMS + col] = o;
                    }
                    int row1 = row0 + 8;
                    if (row1 < NODES) {
                        float2 o;
                        float v2 = fmaf(acc[mt][nt][2], al2.x, be2.x);
                        float v3 = fmaf(acc[mt][nt][3], al2.y, be2.y);
                        o.x = relu ? fmaxf(v2, 0.f) : v2;
                        o.y = relu ? fmaxf(v3, 0.f) : v3;
                        *(float2*)&g_h[row1 * DIMS + col] = o;
                    }
                }
            }
        }
        __syncthreads();   // t dead before next tile's z/W1 fill
    }
}

// ---------------- global mean pool ---------------------------------------------
__global__ void __launch_bounds__(256) pool_kernel(float* __restrict__ out) {
    __shared__ float red[256];
    int g = blockIdx.x;
    int tid = threadIdx.x;
    int d = tid & 63;
    int rg = tid >> 6;
    int lo = 0, hi = NODES;
    while (lo < hi) { int mid = (lo + hi) >> 1; if (g_batI[mid] < g) lo = mid + 1; else hi = mid; }
    int start = lo;
    lo = start; hi = NODES;
    while (lo < hi) { int mid = (lo + hi) >> 1; if (g_batI[mid] < g + 1) lo = mid + 1; else hi = mid; }
    int end = lo;
    float s = 0.f;
    for (int n = start + rg; n < end; n += 4) s += g_h[n * DIMS + d];
    red[tid] = s;
    __syncthreads();
    if (rg == 0) {
        s = red[d] + red[d + 64] + red[d + 128] + red[d + 192];
        float cnt = (float)(end - start);
        out[g * DIMS + d] = s / fmaxf(cnt, 1.0f);
    }
}

// ---------------- launch --------------------------------------------------------
extern "C" void kernel_launch(void* const* d_in, const int* in_sizes, int n_in,
                              void* d_out, int out_size) {
    const float* x    = (const float*)d_in[0];
    const void*  ei   = d_in[1];
    const void*  bat  = d_in[2];
    const float* W1   = (const float*)d_in[3];
    const float* b1   = (const float*)d_in[4];
    const float* g1   = (const float*)d_in[5];
    const float* bt1  = (const float*)d_in[6];
    const float* m1   = (const float*)d_in[7];
    const float* v1   = (const float*)d_in[8];
    const float* W2   = (const float*)d_in[9];
    const float* b2   = (const float*)d_in[10];
    const float* g2   = (const float*)d_in[11];
    const float* bt2  = (const float*)d_in[12];
    const float* m2   = (const float*)d_in[13];
    const float* v2   = (const float*)d_in[14];
    float* out = (float*)d_out;

    cudaFuncSetAttribute(gemm12_kernel, cudaFuncAttributeMaxDynamicSharedMemorySize, L_SMEM);

    static int* dDeg = nullptr;
    static float* dH = nullptr;
    if (!dDeg) {
        cudaGetSymbolAddress((void**)&dDeg, g_deg);
        cudaGetSymbolAddress((void**)&dH, g_h);
    }

    cudaMemsetAsync(dDeg, 0, NODES * sizeof(int));
    big_prep_kernel<<<PREP_GRID, 256>>>(ei, bat, W1, W2,
        b1, g1, bt1, m1, v1, b2, g2, bt2, m2, v2);                // k1
    scan1_kernel<<<SCAN_NB, SCAN_B>>>();                           // k2
    scan23_kernel<<<SCAN_NB, SCAN_B>>>();                          // k3
    fill_kernel<<<(EDGES / 2 + 255) / 256, 256>>>(ei);             // k4 (ncu capture)

    for (int l = 0; l < NLAYER; l++) {
        const float* hin = (l == 0) ? x : (const float*)dH;
        agg_kernel<<<(NODES * 32 + 255) / 256, 256>>>(hin);
        gemm12_kernel<<<GTILES, 256, L_SMEM>>>(l, (l != NLAYER - 1) ? 1 : 0);
    }

    pool_kernel<<<NGRAPH, 256>>>(out);
}

// round 14
// speedup vs baseline: 1.4991x; 1.0012x over previous
#include <cuda_runtime.h>
#include <cuda_bf16.h>
#include <math.h>
#include <stdint.h>

#define NODES 100000
#define EDGES 1600000
#define DIMS  64
#define H2    128
#define NGRAPH 512
#define NLAYER 4
#define BN_EPS 1e-5f

#define SCAN_B 1024
#define SCAN_NB ((NODES + SCAN_B - 1) / SCAN_B)   // 98
#define NTILES ((NODES + 127) / 128)              // 782
#define GTILES3 ((NTILES + 2) / 3)                // 261  -> single wave (<=296)

typedef unsigned long long u64t;

#define FADD2(acc, b) asm("add.rn.f32x2 %0, %0, %1;" : "+l"(acc) : "l"(b))

__device__ __forceinline__ void mma_bf16(float* c, const uint32_t* a, const uint32_t* b) {
    asm volatile("mma.sync.aligned.m16n8k16.row.col.f32.bf16.bf16.f32 "
        "{%0,%1,%2,%3}, {%4,%5,%6,%7}, {%8,%9}, {%0,%1,%2,%3};"
        : "+f"(c[0]), "+f"(c[1]), "+f"(c[2]), "+f"(c[3])
        : "r"(a[0]), "r"(a[1]), "r"(a[2]), "r"(a[3]), "r"(b[0]), "r"(b[1]));
}

__device__ __forceinline__ void split2(float2 z, uint32_t& hi, uint32_t& lo) {
    __nv_bfloat162 h2 = __float22bfloat162_rn(z);
    float2 res = make_float2(z.x - __low2float(h2), z.y - __high2float(h2));
    __nv_bfloat162 l2 = __float22bfloat162_rn(res);
    hi = *(uint32_t*)&h2;
    lo = *(uint32_t*)&l2;
}

__device__ __forceinline__ int detect_is64(const int* p) {
    int odd_nonzero = 0;
    #pragma unroll
    for (int t = 1; t < 32; t += 2) odd_nonzero |= (p[t] != 0);
    return odd_nonzero ? 0 : 1;
}

__device__ __forceinline__ int clampN(int v) {
    return v < 0 ? 0 : (v >= NODES ? NODES - 1 : v);
}

// ---------------- device scratch ----------------------------------------------
__device__ int   g_batI[NODES];
__device__ int   g_deg[NODES];
__device__ int   g_rowstart[NODES + 1];
__device__ int   g_cursor[NODES];
__device__ int   g_srcsorted[EDGES];
__device__ int   g_bsum[256];

__device__ float g_h[NODES * DIMS];
__device__ uint2 g_zh[NODES * 16];
__device__ uint2 g_zl[NODES * 16];

__device__ uint32_t g_w1h[NLAYER][128 * 32], g_w1l[NLAYER][128 * 32];
__device__ uint32_t g_w2h[NLAYER][64 * 64],  g_w2l[NLAYER][64 * 64];

__device__ float g_alpha1[NLAYER][H2], g_beta1[NLAYER][H2];
__device__ float g_alpha2[NLAYER][DIMS], g_beta2[NLAYER][DIMS];

// ---------------- big prep ------------------------------------------------------
#define BATCH_BLKS ((NODES + 255) / 256)
#define HIST_BLKS  ((EDGES / 2 + 255) / 256)
#define W1_BLKS    (NLAYER * 128 * 32 / 256)
#define W2_BLKS    (NLAYER * 64 * 64 / 256)
#define PREP_GRID  (NLAYER + BATCH_BLKS + HIST_BLKS + W1_BLKS + W2_BLKS)

__global__ void big_prep_kernel(const void* __restrict__ ei, const void* __restrict__ bat,
                            const float* __restrict__ W1, const float* __restrict__ W2,
                            const float* __restrict__ b1, const float* __restrict__ g1,
                            const float* __restrict__ bt1, const float* __restrict__ m1,
                            const float* __restrict__ v1,
                            const float* __restrict__ b2, const float* __restrict__ g2,
                            const float* __restrict__ bt2, const float* __restrict__ m2,
                            const float* __restrict__ v2) {
    int bid = blockIdx.x;
    if (bid < NLAYER) {
        int l = bid;
        int c = threadIdx.x;
        if (c < H2) {
            int i = l * H2 + c;
            float s = g1[i] * rsqrtf(v1[i] + BN_EPS);
            g_alpha1[l][c] = s;
            g_beta1[l][c]  = (b1[i] - m1[i]) * s + bt1[i];
        }
        if (c < DIMS) {
            int i = l * DIMS + c;
            float s = g2[i] * rsqrtf(v2[i] + BN_EPS);
            g_alpha2[l][c] = s;
            g_beta2[l][c]  = (b2[i] - m2[i]) * s + bt2[i];
        }
        return;
    }
    bid -= NLAYER;
    if (bid < BATCH_BLKS) {
        __shared__ int s_is64;
        if (threadIdx.x == 0) s_is64 = detect_is64((const int*)ei);
        __syncthreads();
        int i = bid * blockDim.x + threadIdx.x;
        if (i >= NODES) return;
        int b;
        if (s_is64) b = (int)((const long long*)bat)[i];
        else        b = ((const int*)bat)[i];
        g_batI[i] = b < 0 ? 0 : (b >= NGRAPH ? NGRAPH - 1 : b);
        return;
    }
    bid -= BATCH_BLKS;
    if (bid < HIST_BLKS) {
        __shared__ int s_is64;
        if (threadIdx.x == 0) s_is64 = detect_is64((const int*)ei);
        __syncthreads();
        int e0 = (bid * blockDim.x + threadIdx.x) * 2;
        if (e0 >= EDGES) return;
        int d0, d1;
        if (s_is64) {
            longlong2 v = ((const longlong2*)((const long long*)ei + EDGES))[e0 >> 1];
            d0 = (int)v.x; d1 = (int)v.y;
        } else {
            int2 v = ((const int2*)((const int*)ei + EDGES))[e0 >> 1];
            d0 = v.x; d1 = v.y;
        }
        atomicAdd(&g_deg[clampN(d0)], 1);
        atomicAdd(&g_deg[clampN(d1)], 1);
        return;
    }
    bid -= HIST_BLKS;
    if (bid < W1_BLKS) {
        int i = bid * blockDim.x + threadIdx.x;
        int l = i >> 12, rem = i & 4095;
        int n = rem >> 5, kp = rem & 31;
        float2 wv = make_float2(W1[l * DIMS * H2 + (2 * kp) * H2 + n],
                                W1[l * DIMS * H2 + (2 * kp + 1) * H2 + n]);
        uint32_t hi, lo; split2(wv, hi, lo);
        g_w1h[l][rem] = hi;
        g_w1l[l][rem] = lo;
        return;
    }
    bid -= W1_BLKS;
    {
        int i = bid * blockDim.x + threadIdx.x;
        int l = i >> 12, rem = i & 4095;
        int n = rem >> 6, kp = rem & 63;
        float2 wv = make_float2(W2[l * H2 * DIMS + (2 * kp) * DIMS + n],
                                W2[l * H2 * DIMS + (2 * kp + 1) * DIMS + n]);
        uint32_t hi, lo; split2(wv, hi, lo);
        g_w2h[l][rem] = hi;
        g_w2l[l][rem] = lo;
    }
}

// ---------------- scans + fill --------------------------------------------------
__global__ void scan1_kernel() {
    __shared__ int wsum[32];
    int i = blockIdx.x * SCAN_B + threadIdx.x;
    int lane = threadIdx.x & 31, wid = threadIdx.x >> 5;
    int v = (i < NODES) ? g_deg[i] : 0;
    int x = v;
    #pragma unroll
    for (int off = 1; off < 32; off <<= 1) {
        int t = __shfl_up_sync(0xffffffffu, x, off);
        if (lane >= off) x += t;
    }
    if (lane == 31) wsum[wid] = x;
    __syncthreads();
    if (wid == 0) {
        int s = wsum[lane];
        #pragma unroll
        for (int off = 1; off < 32; off <<= 1) {
            int t = __shfl_up_sync(0xffffffffu, s, off);
            if (lane >= off) s += t;
        }
        wsum[lane] = s;
    }
    __syncthreads();
    int incl = x + (wid > 0 ? wsum[wid - 1] : 0);
    if (i < NODES) g_rowstart[i] = incl - v;
    if (threadIdx.x == SCAN_B - 1) g_bsum[blockIdx.x] = incl;
}

__global__ void scan23_kernel() {
    __shared__ int sh[128];
    int t = threadIdx.x;
    if (t < 128) sh[t] = (t < SCAN_NB) ? g_bsum[t] : 0;
    __syncthreads();
    for (int off = 1; off < 128; off <<= 1) {
        int u = 0;
        if (t < 128 && t >= off) u = sh[t - off];
        __syncthreads();
        if (t < 128) sh[t] += u;
        __syncthreads();
    }
    int add = (blockIdx.x == 0) ? 0 : sh[blockIdx.x - 1];
    int i = blockIdx.x * SCAN_B + t;
    if (i < NODES) {
        int r = g_rowstart[i] + add;
        g_rowstart[i] = r;
        g_cursor[i] = r;
    }
    if (i == 0) g_rowstart[NODES] = EDGES;
}

__global__ void fill_kernel(const void* __restrict__ ei) {
    __shared__ int s_is64;
    if (threadIdx.x == 0) s_is64 = detect_is64((const int*)ei);
    __syncthreads();
    int e0 = (blockIdx.x * blockDim.x + threadIdx.x) * 2;
    if (e0 >= EDGES) return;
    int s0, s1, d0, d1;
    if (s_is64) {
        longlong2 sv = ((const longlong2*)ei)[e0 >> 1];
        longlong2 dv = ((const longlong2*)((const long long*)ei + EDGES))[e0 >> 1];
        s0 = (int)sv.x; s1 = (int)sv.y;
        d0 = (int)dv.x; d1 = (int)dv.y;
    } else {
        int2 sv = ((const int2*)ei)[e0 >> 1];
        int2 dv = ((const int2*)((const int*)ei + EDGES))[e0 >> 1];
        s0 = sv.x; s1 = sv.y;
        d0 = dv.x; d1 = dv.y;
    }
    int p0 = atomicAdd(&g_cursor[clampN(d0)], 1);
    g_srcsorted[p0] = clampN(s0);
    int p1 = atomicAdd(&g_cursor[clampN(d1)], 1);
    g_srcsorted[p1] = clampN(s1);
}

// ---------------- aggregation ---------------------------------------------------
__global__ void agg_kernel(const float* __restrict__ hin) {
    int warp = (blockIdx.x * blockDim.x + threadIdx.x) >> 5;
    int lane = threadIdx.x & 31;
    if (warp >= NODES) return;
    int half = lane >> 4;
    int li = lane & 15;
    const float4* __restrict__ h4 = (const float4*)hin;
    float4 acc = make_float4(0.f, 0.f, 0.f, 0.f);
    int rs = g_rowstart[warp], re = g_rowstart[warp + 1];
    for (int base = rs; base < re; base += 32) {
        int cnt = re - base; if (cnt > 32) cnt = 32;
        int s = (base + lane < re) ? g_srcsorted[base + lane] : 0;
        for (int t = 0; t < cnt; t += 2) {
            int idx = t + half;
            int ss = __shfl_sync(0xffffffffu, s, idx);
            if (idx < cnt) {
                float4 v = h4[ss * 16 + li];
                FADD2(*(u64t*)&acc.x, *(u64t*)&v.x);
                FADD2(*(u64t*)&acc.z, *(u64t*)&v.z);
            }
        }
    }
    acc.x += __shfl_down_sync(0xffffffffu, acc.x, 16);
    acc.y += __shfl_down_sync(0xffffffffu, acc.y, 16);
    acc.z += __shfl_down_sync(0xffffffffu, acc.z, 16);
    acc.w += __shfl_down_sync(0xffffffffu, acc.w, 16);
    if (half == 0) {
        float4 self = h4[warp * 16 + li];
        acc.x += self.x; acc.y += self.y; acc.z += self.z; acc.w += self.w;
        uint2 hv, lv;
        split2(make_float2(acc.x, acc.y), hv.x, lv.x);
        split2(make_float2(acc.z, acc.w), hv.y, lv.y);
        g_zh[warp * 16 + li] = hv;
        g_zl[warp * 16 + li] = lv;
    }
}

// ================= fused GEMM1+GEMM2 (3 tiles per CTA, single wave) ============
#define SP1 36
#define SP2 68
#define L_SMEM ((4 * 128 * SP1 + 2 * 64 * SP2) * 4)   // 108544 B

__global__ void __launch_bounds__(256, 2) gemm12_kernel(int layer, int relu)
{
    extern __shared__ uint32_t sm4[];
    uint32_t* zAh = sm4;
    uint32_t* zAl = zAh + 128 * SP1;
    uint32_t* W1h = zAl + 128 * SP1;
    uint32_t* W1l = W1h + 128 * SP1;
    uint32_t* W2h = W1l + 128 * SP1;
    uint32_t* W2l = W2h + 64 * SP2;
    uint32_t* tAh = sm4;               // aliases z+W1 after GEMM1
    uint32_t* tAl = tAh + 128 * SP2;

    int tid = threadIdx.x;
    int w = tid >> 5, lane = tid & 31;
    int mg = w & 3, ng = w >> 2;
    int Rb = mg * 32;
    int r = lane >> 2, q = lane & 3;

    for (int tt = 0; tt < 3; tt++) {
        int tile = blockIdx.x + tt * GTILES3;
        if (tile >= NTILES) break;
        int m0 = tile * 128;

        // z fill (region was t last iteration -> sync at loop end protects)
        for (int i = tid; i < 128 * 16; i += 256) {
            int rr = i >> 4, j = i & 15;
            int node = m0 + rr;
            uint2 hv = make_uint2(0u, 0u), lv = make_uint2(0u, 0u);
            if (node < NODES) { hv = g_zh[node * 16 + j]; lv = g_zl[node * 16 + j]; }
            zAh[rr * SP1 + 2 * j]     = hv.x;
            zAh[rr * SP1 + 2 * j + 1] = hv.y;
            zAl[rr * SP1 + 2 * j]     = lv.x;
            zAl[rr * SP1 + 2 * j + 1] = lv.y;
        }
        // W1 fill (aliased by t, must reload every tile)
        for (int i = tid; i < 128 * 8; i += 256) {
            int n = i >> 3, j = i & 7;
            uint4 vh = ((const uint4*)g_w1h[layer])[i];
            uint4 vl = ((const uint4*)g_w1l[layer])[i];
            uint32_t o = n * SP1 + 4 * j;
            W1h[o] = vh.x; W1h[o + 1] = vh.y; W1h[o + 2] = vh.z; W1h[o + 3] = vh.w;
            W1l[o] = vl.x; W1l[o + 1] = vl.y; W1l[o + 2] = vl.z; W1l[o + 3] = vl.w;
        }
        // W2 fill only on first tile (dedicated region stays resident)
        if (tt == 0) {
            for (int i = tid; i < 64 * 16; i += 256) {
                int n = i >> 4, j = i & 15;
                uint4 vh = ((const uint4*)g_w2h[layer])[i];
                uint4 vl = ((const uint4*)g_w2l[layer])[i];
                uint32_t o = n * SP2 + 4 * j;
                W2h[o] = vh.x; W2h[o + 1] = vh.y; W2h[o + 2] = vh.z; W2h[o + 3] = vh.w;
                W2l[o] = vl.x; W2l[o + 1] = vl.y; W2l[o + 2] = vl.z; W2l[o + 3] = vl.w;
            }
        }
        __syncthreads();

        // ---- GEMM1 [128,64]@[64,128] -> t smem ----
        {
            int Nb = ng * 64;
            float acc[2][8][4];
            #pragma unroll
            for (int mt = 0; mt < 2; mt++)
                #pragma unroll
                for (int nt = 0; nt < 8; nt++)
                    #pragma unroll
                    for (int e = 0; e < 4; e++) acc[mt][nt][e] = 0.f;

            #pragma unroll
            for (int ch = 0; ch < 4; ch++) {
                int K2 = ch * 8;
                uint32_t ah[2][4], al[2][4];
                #pragma unroll
                for (int mt = 0; mt < 2; mt++) {
                    int base = (Rb + mt * 16 + r) * SP1 + K2 + q;
                    ah[mt][0] = zAh[base];
                    ah[mt][1] = zAh[base + 8 * SP1];
                    ah[mt][2] = zAh[base + 4];
                    ah[mt][3] = zAh[base + 8 * SP1 + 4];
                    al[mt][0] = zAl[base];
                    al[mt][1] = zAl[base + 8 * SP1];
                    al[mt][2] = zAl[base + 4];
                    al[mt][3] = zAl[base + 8 * SP1 + 4];
                }
                #pragma unroll
                for (int nt = 0; nt < 8; nt++) {
                    int nb = (Nb + nt * 8 + r) * SP1 + K2 + q;
                    uint32_t bh[2] = { W1h[nb], W1h[nb + 4] };
                    uint32_t bl[2] = { W1l[nb], W1l[nb + 4] };
                    #pragma unroll
                    for (int mt = 0; mt < 2; mt++) {
                        mma_bf16(acc[mt][nt], ah[mt], bh);
                        mma_bf16(acc[mt][nt], ah[mt], bl);
                        mma_bf16(acc[mt][nt], al[mt], bh);
                    }
                }
            }
            __syncthreads();   // z/W1 dead -> reuse for t

            #pragma unroll
            for (int nt = 0; nt < 8; nt++) {
                int col = Nb + nt * 8 + q * 2;
                int kp = col >> 1;
                float2 al2 = *(const float2*)&g_alpha1[layer][col];
                float2 be2 = *(const float2*)&g_beta1[layer][col];
                #pragma unroll
                for (int mt = 0; mt < 2; mt++) {
                    int row0 = Rb + mt * 16 + r;
                    float2 o0, o1;
                    o0.x = fmaxf(fmaf(acc[mt][nt][0], al2.x, be2.x), 0.f);
                    o0.y = fmaxf(fmaf(acc[mt][nt][1], al2.y, be2.y), 0.f);
                    o1.x = fmaxf(fmaf(acc[mt][nt][2], al2.x, be2.x), 0.f);
                    o1.y = fmaxf(fmaf(acc[mt][nt][3], al2.y, be2.y), 0.f);
                    uint32_t hi, lo;
                    split2(o0, hi, lo);
                    tAh[row0 * SP2 + kp] = hi;
                    tAl[row0 * SP2 + kp] = lo;
                    split2(o1, hi, lo);
                    tAh[(row0 + 8) * SP2 + kp] = hi;
                    tAl[(row0 + 8) * SP2 + kp] = lo;
                }
            }
        }
        __syncthreads();

        // ---- GEMM2 [128,128]@[128,64] -> g_h ----
        {
            int Nb = ng * 32;
            float acc[2][4][4];
            #pragma unroll
            for (int mt = 0; mt < 2; mt++)
                #pragma unroll
                for (int nt = 0; nt < 4; nt++)
                    #pragma unroll
                    for (int e = 0; e < 4; e++) acc[mt][nt][e] = 0.f;

            #pragma unroll
            for (int ch = 0; ch < 8; ch++) {
                int K2 = ch * 8;
                uint32_t ah[2][4], al[2][4];
                #pragma unroll
                for (int mt = 0; mt < 2; mt++) {
                    int base = (Rb + mt * 16 + r) * SP2 + K2 + q;
                    ah[mt][0] = tAh[base];
                    ah[mt][1] = tAh[base + 8 * SP2];
                    ah[mt][2] = tAh[base + 4];
                    ah[mt][3] = tAh[base + 8 * SP2 + 4];
                    al[mt][0] = tAl[base];
                    al[mt][1] = tAl[base + 8 * SP2];
                    al[mt][2] = tAl[base + 4];
                    al[mt][3] = tAl[base + 8 * SP2 + 4];
                }
                #pragma unroll
                for (int nt = 0; nt < 4; nt++) {
                    int nb = (Nb + nt * 8 + r) * SP2 + K2 + q;
                    uint32_t bh[2] = { W2h[nb], W2h[nb + 4] };
                    uint32_t bl[2] = { W2l[nb], W2l[nb + 4] };
                    #pragma unroll
                    for (int mt = 0; mt < 2; mt++) {
                        mma_bf16(acc[mt][nt], ah[mt], bh);
                        mma_bf16(acc[mt][nt], ah[mt], bl);
                        mma_bf16(acc[mt][nt], al[mt], bh);
                    }
                }
            }

            #pragma unroll
            for (int nt = 0; nt < 4; nt++) {
                int col = Nb + nt * 8 + q * 2;
                float2 al2 = *(const float2*)&g_alpha2[layer][col];
                float2 be2 = *(const float2*)&g_beta2[layer][col];
                #pragma unroll
                for (int mt = 0; mt < 2; mt++) {
                    int row0 = m0 + Rb + mt * 16 + r;
                    if (row0 < NODES) {
                        float2 o;
                        float v0 = fmaf(acc[mt][nt][0], al2.x, be2.x);
                        float v1 = fmaf(acc[mt][nt][1], al2.y, be2.y);
                        o.x = relu ? fmaxf(v0, 0.f) : v0;
                        o.y = relu ? fmaxf(v1, 0.f) : v1;
                        *(float2*)&g_h[row0 * DIMS + col] = o;
                    }
                    int row1 = row0 + 8;
                    if (row1 < NODES) {
                        float2 o;
                        float v2 = fmaf(acc[mt][nt][2], al2.x, be2.x);
                        float v3 = fmaf(acc[mt][nt][3], al2.y, be2.y);
                        o.x = relu ? fmaxf(v2, 0.f) : v2;
                        o.y = relu ? fmaxf(v3, 0.f) : v3;
                        *(float2*)&g_h[row1 * DIMS + col] = o;
                    }
                }
            }
        }
        __syncthreads();   // t dead before next tile's z/W1 fill
    }
}

// ---------------- global mean pool ---------------------------------------------
__global__ void __launch_bounds__(256) pool_kernel(float* __restrict__ out) {
    __shared__ float red[256];
    int g = blockIdx.x;
    int tid = threadIdx.x;
    int d = tid & 63;
    int rg = tid >> 6;
    int lo = 0, hi = NODES;
    while (lo < hi) { int mid = (lo + hi) >> 1; if (g_batI[mid] < g) lo = mid + 1; else hi = mid; }
    int start = lo;
    lo = start; hi = NODES;
    while (lo < hi) { int mid = (lo + hi) >> 1; if (g_batI[mid] < g + 1) lo = mid + 1; else hi = mid; }
    int end = lo;
    float s = 0.f;
    for (int n = start + rg; n < end; n += 4) s += g_h[n * DIMS + d];
    red[tid] = s;
    __syncthreads();
    if (rg == 0) {
        s = red[d] + red[d + 64] + red[d + 128] + red[d + 192];
        float cnt = (float)(end - start);
        out[g * DIMS + d] = s / fmaxf(cnt, 1.0f);
    }
}

// ---------------- launch --------------------------------------------------------
extern "C" void kernel_launch(void* const* d_in, const int* in_sizes, int n_in,
                              void* d_out, int out_size) {
    const float* x    = (const float*)d_in[0];
    const void*  ei   = d_in[1];
    const void*  bat  = d_in[2];
    const float* W1   = (const float*)d_in[3];
    const float* b1   = (const float*)d_in[4];
    const float* g1   = (const float*)d_in[5];
    const float* bt1  = (const float*)d_in[6];
    const float* m1   = (const float*)d_in[7];
    const float* v1   = (const float*)d_in[8];
    const float* W2   = (const float*)d_in[9];
    const float* b2   = (const float*)d_in[10];
    const float* g2   = (const float*)d_in[11];
    const float* bt2  = (const float*)d_in[12];
    const float* m2   = (const float*)d_in[13];
    const float* v2   = (const float*)d_in[14];
    float* out = (float*)d_out;

    cudaFuncSetAttribute(gemm12_kernel, cudaFuncAttributeMaxDynamicSharedMemorySize, L_SMEM);

    static int* dDeg = nullptr;
    static float* dH = nullptr;
    if (!dDeg) {
        cudaGetSymbolAddress((void**)&dDeg, g_deg);
        cudaGetSymbolAddress((void**)&dH, g_h);
    }

    cudaMemsetAsync(dDeg, 0, NODES * sizeof(int));
    big_prep_kernel<<<PREP_GRID, 256>>>(ei, bat, W1, W2,
        b1, g1, bt1, m1, v1, b2, g2, bt2, m2, v2);                // k1
    scan1_kernel<<<SCAN_NB, SCAN_B>>>();                           // k2
    scan23_kernel<<<SCAN_NB, SCAN_B>>>();                          // k3
    fill_kernel<<<(EDGES / 2 + 255) / 256, 256>>>(ei);             // k4 (ncu capture)

    for (int l = 0; l < NLAYER; l++) {
        const float* hin = (l == 0) ? x : (const float*)dH;
        agg_kernel<<<(NODES * 32 + 255) / 256, 256>>>(hin);
        gemm12_kernel<<<GTILES3, 256, L_SMEM>>>(l, (l != NLAYER - 1) ? 1 : 0);
    }

    pool_kernel<<<NGRAPH, 256>>>(out);
}